// round 11
// baseline (speedup 1.0000x reference)
#include <cuda_runtime.h>
#include <stdint.h>

#define BB 4
#define NN 2000
#define CC 80
#define NCLS 81
#define KPRE 2000
#define MAXOUT 100
#define MAXC 256
#define NHIST 5120
#define HBASE 0x1EA66
#define SCORE_THR 0.05f
#define IOU_THR 0.5f
#define MAX_RATIO 4.135166556742356f

typedef unsigned long long u64;

// ---------------- scratch (device globals; self-cleaning, no allocation) -------
__device__ int g_hist[BB][NHIST];        // zeroed by k_emit
__device__ int g_ccnt[BB][CC];           // zeroed by k_emit
__device__ u64 g_ckeys[BB][CC][MAXC];    // only [0,cnt) read
__device__ u64 g_kkeys[BB][2048];        // only [0,kcnt) read
__device__ int g_kcnt[BB];               // zeroed by k_emit

__device__ __forceinline__ int bucket_of(unsigned bits) {
    int b = (int)(bits >> 13) - HBASE;
    return min(NHIST - 1, max(0, b));
}

// exact reference fp decode (no FMA contraction)
__device__ __forceinline__ void decode_one(
    u64 key, int img,
    const float* __restrict__ reg, const float* __restrict__ props,
    float h, float w, float maxhw1,
    float4* bx, float4* ob, float* ar)
{
    int flat = (int)(~(unsigned)key);
    int p = flat / CC, c = flat % CC;
    const float* pb = props + ((size_t)img * NN + p) * 4;
    const float* dd = reg + (((size_t)img * NN + p) * CC + c) * 4;

    float dx = __fmul_rn(dd[0], 0.1f);
    float dy = __fmul_rn(dd[1], 0.1f);
    float dw = fminf(fmaxf(__fmul_rn(dd[2], 0.2f), -MAX_RATIO), MAX_RATIO);
    float dh = fminf(fmaxf(__fmul_rn(dd[3], 0.2f), -MAX_RATIO), MAX_RATIO);

    float px = __fmul_rn(__fadd_rn(pb[0], pb[2]), 0.5f);
    float py = __fmul_rn(__fadd_rn(pb[1], pb[3]), 0.5f);
    float pw = __fsub_rn(pb[2], pb[0]);
    float ph = __fsub_rn(pb[3], pb[1]);

    float gx = __fadd_rn(px, __fmul_rn(pw, dx));
    float gy = __fadd_rn(py, __fmul_rn(ph, dy));
    float gw = __fmul_rn(pw, expf(dw));
    float gh = __fmul_rn(ph, expf(dh));
    float hx = __fmul_rn(gw, 0.5f);
    float hy = __fmul_rn(gh, 0.5f);

    float x1 = fminf(fmaxf(__fsub_rn(gx, hx), 0.0f), w);
    float y1 = fminf(fmaxf(__fsub_rn(gy, hy), 0.0f), h);
    float x2 = fminf(fmaxf(__fadd_rn(gx, hx), 0.0f), w);
    float y2 = fminf(fmaxf(__fadd_rn(gy, hy), 0.0f), h);

    *bx = make_float4(x1, y1, x2, y2);
    float off = __fmul_rn((float)c, maxhw1);
    float4 o = make_float4(__fadd_rn(x1, off), __fadd_rn(y1, off),
                           __fadd_rn(x2, off), __fadd_rn(y2, off));
    *ob = o;
    *ar = __fmul_rn(__fsub_rn(o.z, o.x), __fsub_rn(o.w, o.y));
}

__device__ __forceinline__ bool iou_gt(float4 bi, float ai, float4 bj, float aj) {
    float ltx = fmaxf(bi.x, bj.x), lty = fmaxf(bi.y, bj.y);
    float rbx = fminf(bi.z, bj.z), rby = fminf(bi.w, bj.w);
    float wx = fmaxf(__fsub_rn(rbx, ltx), 0.0f);
    float wy = fmaxf(__fsub_rn(rby, lty), 0.0f);
    float inter = __fmul_rn(wx, wy);
    float den = __fadd_rn(__fsub_rn(__fadd_rn(ai, aj), inter), 1e-6f);
    return __fdiv_rn(inter, den) > IOU_THR;
}

// -------- softmax (2 rows/warp) + threshold + per-class scatter + histogram ----
__global__ void k_softmax(const float* __restrict__ cls) {
    int gw = (blockIdx.x * blockDim.x + threadIdx.x) >> 5;
    int lane = threadIdx.x & 31;
    if (gw >= BB * NN / 2) return;
    int pr0 = gw * 2;
    int img = pr0 / NN;
    const float* rowA = cls + (size_t)pr0 * NCLS;
    const float* rowB = rowA + NCLS;

    float a0 = rowA[lane], a1 = rowA[lane + 32];
    float a2 = (lane < NCLS - 64) ? rowA[lane + 64] : -1e30f;
    float b0 = rowB[lane], b1 = rowB[lane + 32];
    float b2 = (lane < NCLS - 64) ? rowB[lane + 64] : -1e30f;

    float mA = fmaxf(fmaxf(a0, a1), a2);
    float mB = fmaxf(fmaxf(b0, b1), b2);
    #pragma unroll
    for (int o = 16; o; o >>= 1) {
        mA = fmaxf(mA, __shfl_xor_sync(0xffffffffu, mA, o));
        mB = fmaxf(mB, __shfl_xor_sync(0xffffffffu, mB, o));
    }
    float eA0 = expf(a0 - mA), eA1 = expf(a1 - mA);
    float eA2 = (lane < NCLS - 64) ? expf(a2 - mA) : 0.0f;
    float eB0 = expf(b0 - mB), eB1 = expf(b1 - mB);
    float eB2 = (lane < NCLS - 64) ? expf(b2 - mB) : 0.0f;
    float sA = eA0 + eA1 + eA2;
    float sB = eB0 + eB1 + eB2;
    #pragma unroll
    for (int o = 16; o; o >>= 1) {
        sA += __shfl_xor_sync(0xffffffffu, sA, o);
        sB += __shfl_xor_sync(0xffffffffu, sB, o);
    }
    float sc[6];
    sc[0] = __fdiv_rn(eA0, sA); sc[1] = __fdiv_rn(eA1, sA); sc[2] = __fdiv_rn(eA2, sA);
    sc[3] = __fdiv_rn(eB0, sB); sc[4] = __fdiv_rn(eB1, sB); sc[5] = __fdiv_rn(eB2, sB);

    #pragma unroll
    for (int g = 0; g < 6; g++) {
        int grp = g % 3;
        bool pr = (grp < 2) ? (sc[g] > SCORE_THR)
                            : ((lane < CC - 64) && sc[g] > SCORE_THR);
        if (pr) {
            int p = pr0 + (g / 3) - img * NN;
            int c = lane + grp * 32;
            unsigned sb = __float_as_uint(sc[g]);
            unsigned flat = (unsigned)(p * CC + c);
            u64 key = ((u64)sb << 32) | (u64)(~flat);
            int pos = atomicAdd(&g_ccnt[img][c], 1);
            if (pos < MAXC) {
                g_ckeys[img][c][pos] = key;
                atomicAdd(&g_hist[img][bucket_of(sb)], 1);
            }
        }
    }
}

// -------- NMS: cutoff (redundant per block) + warp-per-class sort+NMS ----------
#define CHK (NHIST / 256)   /* 20 buckets per thread */
__global__ void k_nms(const float* __restrict__ reg,
                      const float* __restrict__ props,
                      const int* __restrict__ hw) {
    __shared__ int s_h[NHIST];          // hist by DESC rank
    __shared__ u64 s_wk[8][MAXC];
    __shared__ u64 s_bk[256];
    __shared__ int s_cnt[80];
    __shared__ int s_wsum[8];
    __shared__ int s_total, s_m, s_bcut, s_krem;
    __shared__ u64 s_cut;

    int img = blockIdx.x;
    int t = threadIdx.x;  // 256
    int lane = t & 31, w = t >> 5;
    unsigned lmlt = (1u << lane) - 1u;

    if (t < 80) s_cnt[t] = min(g_ccnt[img][t], MAXC);
    if (t == 0) { s_m = 0; s_bcut = -1; s_cut = 1ULL; }

    // load hist (desc-rank order) + chunk sum
    int csum = 0;
    #pragma unroll
    for (int u = 0; u < CHK; u++) {
        int r = t * CHK + u;
        int v = g_hist[img][NHIST - 1 - r];
        s_h[r] = v;
        csum += v;
    }
    // block scan of chunk sums (ascending rank)
    int ws = csum;
    #pragma unroll
    for (int o = 1; o < 32; o <<= 1) {
        int v = __shfl_up_sync(0xffffffffu, ws, o);
        if (lane >= o) ws += v;
    }
    if (lane == 31) s_wsum[w] = ws;
    __syncthreads();
    if (t == 0) {
        int a = 0;
        for (int i = 0; i < 8; i++) { int v = s_wsum[i]; s_wsum[i] = a; a += v; }
        s_total = a;
    }
    __syncthreads();
    int before = s_wsum[w] + (ws - csum);  // # keys in strictly-higher buckets than my chunk
    int total = s_total;

    if (total > KPRE) {
        // find boundary bucket (the one containing the 2000th key)
        int acc = before;
        #pragma unroll
        for (int u = 0; u < CHK; u++) {
            int r = t * CHK + u;
            int v = s_h[r];
            if (acc < KPRE && acc + v >= KPRE) {
                s_bcut = NHIST - 1 - r;   // unique thread
                s_krem = KPRE - acc;      // need k_rem largest within this bucket
            }
            acc += v;
        }
        __syncthreads();
        int bcut = s_bcut, krem = s_krem;
        // collect keys in boundary bucket
        for (int s = t; s < 80 * MAXC; s += 256) {
            int c = s >> 8, i = s & (MAXC - 1);
            if (i < s_cnt[c]) {
                u64 k = g_ckeys[img][c][i];
                if (bucket_of((unsigned)(k >> 32)) == bcut) {
                    int pos = atomicAdd(&s_m, 1);
                    if (pos < 256) s_bk[pos] = k;
                }
            }
        }
        __syncthreads();
        int m = min(s_m, 256);
        // rank-select the krem-th largest (1-indexed)
        for (int e = t; e < m; e += 256) {
            u64 ke = s_bk[e];
            int r = 0;
            for (int j = 0; j < m; j++) r += (s_bk[j] > ke);
            if (r == krem - 1) s_cut = ke;
        }
    }
    __syncthreads();
    u64 cutoff = s_cut;

    // ---- warp per class ----
    int c = blockIdx.y * 8 + w;
    int cnt = s_cnt[c];
    float h = (float)hw[img * 2 + 0];
    float wd = (float)hw[img * 2 + 1];
    float maxhw1 = __fadd_rn(fmaxf(h, wd), 1.0f);

    // filter + compact valid keys
    int n = 0;
    for (int u = 0; u * 32 < cnt; u++) {
        int pos = u * 32 + lane;
        u64 k = (pos < cnt) ? g_ckeys[img][c][pos] : 0ULL;
        bool val = (pos < cnt) && (k >= cutoff);
        unsigned mk = __ballot_sync(0xffffffffu, val);
        if (val) s_wk[w][n + __popc(mk & lmlt)] = k;
        n += __popc(mk);
    }
    __syncwarp();
    if (n > 0) {
        int nr = (n + 31) >> 5;
        // rank-sort descending via smem broadcast
        u64 kq[8];
        int rq[8];
        #pragma unroll
        for (int u = 0; u < 8; u++) {
            int pos = u * 32 + lane;
            kq[u] = (u < nr && pos < n) ? s_wk[w][pos] : 0ULL;
            rq[u] = 0;
        }
        __syncwarp();
        for (int j = 0; j < n; j++) {
            u64 kj = s_wk[w][j];
            #pragma unroll
            for (int u = 0; u < 8; u++) {
                if (u >= nr) break;
                rq[u] += (kj > kq[u]);
            }
        }
        __syncwarp();
        #pragma unroll
        for (int u = 0; u < 8; u++) {
            if (u >= nr) break;
            int pos = u * 32 + lane;
            if (pos < n) s_wk[w][rq[u]] = kq[u];
        }
        __syncwarp();

        // decode into registers + greedy register NMS
        float4 bb[8];
        float aa[8];
        unsigned kmask = 0;
        #pragma unroll
        for (int u = 0; u < 8; u++) {
            bb[u] = make_float4(0, 0, 0, 0);
            aa[u] = 0.0f;
            if (u < nr) {
                int pos = u * 32 + lane;
                if (pos < n) {
                    float4 bx;
                    decode_one(s_wk[w][pos], img, reg, props, h, wd, maxhw1,
                               &bx, &bb[u], &aa[u]);
                    kmask |= 1u << u;
                }
            }
        }
        #pragma unroll
        for (int u = 0; u < 8; u++) {
            if (u >= nr) break;
            int ilim = min(n - u * 32, 32);
            for (int li = 0; li < ilim; li++) {
                unsigned am = __ballot_sync(0xffffffffu, (kmask >> u) & 1u);
                if (!((am >> li) & 1u)) continue;
                int i = u * 32 + li;
                float bix = __shfl_sync(0xffffffffu, bb[u].x, li);
                float biy = __shfl_sync(0xffffffffu, bb[u].y, li);
                float biz = __shfl_sync(0xffffffffu, bb[u].z, li);
                float biw = __shfl_sync(0xffffffffu, bb[u].w, li);
                float ai  = __shfl_sync(0xffffffffu, aa[u], li);
                float4 bi = make_float4(bix, biy, biz, biw);
                #pragma unroll
                for (int v = 0; v < 8; v++) {
                    if (v >= nr) break;
                    int pos = v * 32 + lane;
                    if (pos > i && ((kmask >> v) & 1u)) {
                        if (iou_gt(bi, ai, bb[v], aa[v]))
                            kmask &= ~(1u << v);
                    }
                }
            }
        }
        // publish kept keys (order irrelevant; k_emit re-ranks)
        #pragma unroll
        for (int u = 0; u < 8; u++) {
            if (u >= nr) break;
            bool kept = (kmask >> u) & 1u;
            unsigned mk = __ballot_sync(0xffffffffu, kept);
            int tk = __popc(mk);
            int base = 0;
            if (lane == 0 && tk) base = atomicAdd(&g_kcnt[img], tk);
            base = __shfl_sync(0xffffffffu, base, 0);
            if (kept) {
                int r = base + __popc(mk & lmlt);
                if (r < 2048) g_kkeys[img][r] = s_wk[w][u * 32 + lane];
            }
        }
    }
}

// -------- emit: rank kept keys, decode top-100, write output, clean scratch ----
__global__ void k_emit(const float* __restrict__ reg,
                       const float* __restrict__ props,
                       const int* __restrict__ hw,
                       float* __restrict__ out) {
    __shared__ u64 s_k[2048];
    __shared__ int s_n;
    int img = blockIdx.x, t = threadIdx.x;  // 256

    if (t == 0) s_n = min(g_kcnt[img], 2048);
    __syncthreads();
    int n = s_n;
    for (int e = t; e < n; e += 256) s_k[e] = g_kkeys[img][e];
    __syncthreads();

    float h = (float)hw[img * 2 + 0];
    float w = (float)hw[img * 2 + 1];
    float maxhw1 = __fadd_rn(fmaxf(h, w), 1.0f);

    for (int e = t; e < n; e += 256) {
        u64 ke = s_k[e];
        int r = 0;
        for (int j = 0; j < n; j++) r += (s_k[j] > ke);
        if (r < MAXOUT) {
            float4 bx, ob;
            float ar;
            decode_one(ke, img, reg, props, h, w, maxhw1, &bx, &ob, &ar);
            float sc = __uint_as_float((unsigned)(ke >> 32));
            float lb = (float)((int)(~(unsigned)ke) % CC);
            float* bo = out + (size_t)(img * MAXOUT + r) * 4;
            bo[0] = bx.x; bo[1] = bx.y; bo[2] = bx.z; bo[3] = bx.w;
            out[BB * MAXOUT * 4 + img * MAXOUT + r] = sc;
            out[BB * MAXOUT * 5 + img * MAXOUT + r] = lb;
        }
    }
    // pad unfilled slots
    if (t < MAXOUT && t >= n) {
        float* bo = out + (size_t)(img * MAXOUT + t) * 4;
        bo[0] = 0.0f; bo[1] = 0.0f; bo[2] = 0.0f; bo[3] = 0.0f;
        out[BB * MAXOUT * 4 + img * MAXOUT + t] = 0.0f;
        out[BB * MAXOUT * 5 + img * MAXOUT + t] = -1.0f;
    }
    // self-clean scratch for next run
    for (int i = t; i < NHIST; i += 256) g_hist[img][i] = 0;
    if (t < 80) g_ccnt[img][t] = 0;
    if (t == 0) g_kcnt[img] = 0;
}

// ---------------- launch (3 kernels) -------------------------------------------
extern "C" void kernel_launch(void* const* d_in, const int* in_sizes, int n_in,
                              void* d_out, int out_size) {
    const float* cls = (const float*)d_in[0];
    const float* reg = (const float*)d_in[1];
    const float* props = (const float*)d_in[2];
    const int* hw = (const int*)d_in[3];
    float* out = (float*)d_out;

    k_softmax<<<(BB * NN / 2 * 32 + 255) / 256, 256>>>(cls);
    dim3 ng(BB, 10);
    k_nms<<<ng, 256>>>(reg, props, hw);
    k_emit<<<BB, 256>>>(reg, props, hw, out);
}

// round 12
// speedup vs baseline: 3.9175x; 3.9175x over previous
#include <cuda_runtime.h>
#include <stdint.h>

#define BB 4
#define NN 2000
#define CC 80
#define NCLS 81
#define KPRE 2000
#define MAXOUT 100
#define CAP 8192
#define NHIST 5120
#define HBASE 0x1EA66
#define SCORE_THR 0.05f
#define IOU_THR 0.5f
#define MAX_RATIO 4.135166556742356f

// ---------------- scratch (device globals; self-cleaning, no allocation) -------
__device__ int g_cnt[BB];            // zeroed by k_sortgroup after read
__device__ int g_hist[BB][NHIST];    // zeroed by k_sortgroup after read
__device__ unsigned long long g_keys[BB][CAP];    // only [0,cnt) read
__device__ unsigned long long g_skeys[BB][2048];  // fully rewritten each run
__device__ unsigned short g_ord[BB][2048];        // [st,st+tot) read only
__device__ int g_start[BB][CC];                   // fully rewritten
__device__ int g_tot[BB][CC];                     // fully rewritten
__device__ unsigned g_kept[BB][64];               // fully rewritten
__device__ float4 g_box[BB][2048];                // kept entries written then read
__device__ float4 g_ob[BB][2048];                 // slow path only
__device__ float  g_ar[BB][2048];                 // slow path only
__device__ int g_done[BB];                        // reset by emitting block

__device__ __forceinline__ int bucket_of(unsigned bits) {
    int b = (int)(bits >> 13) - HBASE;
    return min(NHIST - 1, max(0, b));
}

// exact reference fp decode (no FMA contraction)
__device__ __forceinline__ void decode_one(
    unsigned long long key, int img,
    const float* __restrict__ reg, const float* __restrict__ props,
    float h, float w, float maxhw1,
    float4* bx, float4* ob, float* ar)
{
    int flat = (int)(~(unsigned)key);
    int p = flat / CC, c = flat % CC;
    const float* pb = props + ((size_t)img * NN + p) * 4;
    const float* dd = reg + (((size_t)img * NN + p) * CC + c) * 4;

    float dx = __fmul_rn(dd[0], 0.1f);
    float dy = __fmul_rn(dd[1], 0.1f);
    float dw = fminf(fmaxf(__fmul_rn(dd[2], 0.2f), -MAX_RATIO), MAX_RATIO);
    float dh = fminf(fmaxf(__fmul_rn(dd[3], 0.2f), -MAX_RATIO), MAX_RATIO);

    float px = __fmul_rn(__fadd_rn(pb[0], pb[2]), 0.5f);
    float py = __fmul_rn(__fadd_rn(pb[1], pb[3]), 0.5f);
    float pw = __fsub_rn(pb[2], pb[0]);
    float ph = __fsub_rn(pb[3], pb[1]);

    float gx = __fadd_rn(px, __fmul_rn(pw, dx));
    float gy = __fadd_rn(py, __fmul_rn(ph, dy));
    float gw = __fmul_rn(pw, expf(dw));
    float gh = __fmul_rn(ph, expf(dh));
    float hx = __fmul_rn(gw, 0.5f);
    float hy = __fmul_rn(gh, 0.5f);

    float x1 = fminf(fmaxf(__fsub_rn(gx, hx), 0.0f), w);
    float y1 = fminf(fmaxf(__fsub_rn(gy, hy), 0.0f), h);
    float x2 = fminf(fmaxf(__fadd_rn(gx, hx), 0.0f), w);
    float y2 = fminf(fmaxf(__fadd_rn(gy, hy), 0.0f), h);

    *bx = make_float4(x1, y1, x2, y2);
    float off = __fmul_rn((float)c, maxhw1);
    float4 o = make_float4(__fadd_rn(x1, off), __fadd_rn(y1, off),
                           __fadd_rn(x2, off), __fadd_rn(y2, off));
    *ob = o;
    *ar = __fmul_rn(__fsub_rn(o.z, o.x), __fsub_rn(o.w, o.y));
}

__device__ __forceinline__ bool iou_gt(float4 bi, float ai, float4 bj, float aj) {
    float ltx = fmaxf(bi.x, bj.x), lty = fmaxf(bi.y, bj.y);
    float rbx = fminf(bi.z, bj.z), rby = fminf(bi.w, bj.w);
    float wx = fmaxf(__fsub_rn(rbx, ltx), 0.0f);
    float wy = fmaxf(__fsub_rn(rby, lty), 0.0f);
    float inter = __fmul_rn(wx, wy);
    float den = __fadd_rn(__fsub_rn(__fadd_rn(ai, aj), inter), 1e-6f);
    return __fdiv_rn(inter, den) > IOU_THR;
}

// -------- softmax (2 rows/warp) + threshold + compact + histogram --------------
__global__ void k_softmax(const float* __restrict__ cls) {
    int gw = (blockIdx.x * blockDim.x + threadIdx.x) >> 5;
    int lane = threadIdx.x & 31;
    if (gw >= BB * NN / 2) return;
    int pr0 = gw * 2;
    int img = pr0 / NN;
    const float* rowA = cls + (size_t)pr0 * NCLS;
    const float* rowB = rowA + NCLS;

    float a0 = rowA[lane], a1 = rowA[lane + 32];
    float a2 = (lane < NCLS - 64) ? rowA[lane + 64] : -1e30f;
    float b0 = rowB[lane], b1 = rowB[lane + 32];
    float b2 = (lane < NCLS - 64) ? rowB[lane + 64] : -1e30f;

    float mA = fmaxf(fmaxf(a0, a1), a2);
    float mB = fmaxf(fmaxf(b0, b1), b2);
    #pragma unroll
    for (int o = 16; o; o >>= 1) {
        mA = fmaxf(mA, __shfl_xor_sync(0xffffffffu, mA, o));
        mB = fmaxf(mB, __shfl_xor_sync(0xffffffffu, mB, o));
    }
    float eA0 = expf(a0 - mA), eA1 = expf(a1 - mA);
    float eA2 = (lane < NCLS - 64) ? expf(a2 - mA) : 0.0f;
    float eB0 = expf(b0 - mB), eB1 = expf(b1 - mB);
    float eB2 = (lane < NCLS - 64) ? expf(b2 - mB) : 0.0f;
    float sA = eA0 + eA1 + eA2;
    float sB = eB0 + eB1 + eB2;
    #pragma unroll
    for (int o = 16; o; o >>= 1) {
        sA += __shfl_xor_sync(0xffffffffu, sA, o);
        sB += __shfl_xor_sync(0xffffffffu, sB, o);
    }
    float sc[6];
    sc[0] = __fdiv_rn(eA0, sA); sc[1] = __fdiv_rn(eA1, sA); sc[2] = __fdiv_rn(eA2, sA);
    sc[3] = __fdiv_rn(eB0, sB); sc[4] = __fdiv_rn(eB1, sB); sc[5] = __fdiv_rn(eB2, sB);
    unsigned bal[6];
    int pc[6];
    int tot = 0;
    #pragma unroll
    for (int g = 0; g < 6; g++) {
        int grp = g % 3;
        bool pr = (grp < 2) ? (sc[g] > SCORE_THR)
                            : ((lane < CC - 64) && sc[g] > SCORE_THR);
        bal[g] = __ballot_sync(0xffffffffu, pr);
        pc[g] = __popc(bal[g]);
        tot += pc[g];
    }
    int base = 0;
    if (lane == 0 && tot) base = atomicAdd(&g_cnt[img], tot);
    base = __shfl_sync(0xffffffffu, base, 0);
    unsigned lm = (1u << lane) - 1u;
    #pragma unroll
    for (int g = 0; g < 6; g++) {
        if (bal[g] & (1u << lane)) {
            int grp = g % 3;
            int p = pr0 + (g / 3) - img * NN;
            int c = lane + grp * 32;
            int rank = __popc(bal[g] & lm);
            #pragma unroll
            for (int gg = 0; gg < 6; gg++) if (gg < g) rank += pc[gg];
            int pos = base + rank;
            if (pos < CAP) {
                unsigned flat = (unsigned)(p * CC + c);
                unsigned sb = __float_as_uint(sc[g]);
                g_keys[img][pos] =
                    ((unsigned long long)sb << 32) | (unsigned long long)(~flat);
                atomicAdd(&g_hist[img][bucket_of(sb)], 1);
            }
        }
    }
}

// -------- sort + class grouping (1 block/img) ----------------------------------
#define SM_OFF   0        /* int[5120] */
#define SM_BC    20480    /* int[5120] */
#define SM_SK    40960    /* u64[2048] */
#define SM_LAB   57344    /* u16[2048] */
#define SM_ORD   61440    /* u16[2048] */
#define SM_CCNT  65536    /* int[32*80] */
#define SM_TOT   75776    /* int[80] */
#define SM_START 76096    /* int[80] */
#define SM_WTOT  76416    /* int[32] */
#define SMEMSZ   76544
#define SCAN_U (NHIST / 1024)   /* 5 */

__global__ void k_sortgroup() {
    extern __shared__ unsigned char dyn[];
    int* s_off = (int*)(dyn + SM_OFF);
    int* s_bc = (int*)(dyn + SM_BC);
    unsigned long long* s_sk = (unsigned long long*)(dyn + SM_SK);
    unsigned short* s_lab = (unsigned short*)(dyn + SM_LAB);
    unsigned short* s_ord = (unsigned short*)(dyn + SM_ORD);
    int* s_ccnt = (int*)(dyn + SM_CCNT);
    int* s_tot = (int*)(dyn + SM_TOT);
    int* s_start = (int*)(dyn + SM_START);
    int* s_wtot = (int*)(dyn + SM_WTOT);

    int img = blockIdx.x, t = threadIdx.x;  // 1024
    int lane = t & 31, wid = t >> 5;
    unsigned lmlt = (1u << lane) - 1u;

    // phase 1: histogram read+zero, suffix scan
    int cnt[SCAN_U];
    int tsum = 0;
    #pragma unroll
    for (int u = 0; u < SCAN_U; u++) {
        int b = NHIST - 1 - (t * SCAN_U + u);
        cnt[u] = g_hist[img][b];
        g_hist[img][b] = 0;
        s_bc[b] = 0;
        tsum += cnt[u];
    }
    int ws = tsum;
    #pragma unroll
    for (int o = 1; o < 32; o <<= 1) {
        int v = __shfl_up_sync(0xffffffffu, ws, o);
        if (lane >= o) ws += v;
    }
    if (lane == 31) s_wtot[wid] = ws;
    __syncthreads();
    if (wid == 0) {
        int v = s_wtot[lane];
        int sv = v;
        #pragma unroll
        for (int o = 1; o < 32; o <<= 1) {
            int x = __shfl_up_sync(0xffffffffu, sv, o);
            if (lane >= o) sv += x;
        }
        s_wtot[lane] = sv - v;
    }
    __syncthreads();
    int base = s_wtot[wid] + (ws - tsum);
    #pragma unroll
    for (int u = 0; u < SCAN_U; u++) {
        int b = NHIST - 1 - (t * SCAN_U + u);
        s_off[b] = base;
        base += cnt[u];
    }
    int total = min(g_cnt[img], CAP);
    if (t == 0) g_cnt[img] = 0;
    s_sk[t] = 0ULL; s_sk[t + 1024] = 0ULL;
    __syncthreads();

    // phase 2: scatter
    for (int e = t; e < total; e += 1024) {
        unsigned long long key = g_keys[img][e];
        int b = bucket_of((unsigned)(key >> 32));
        int o = s_off[b];
        if (o < 2048) {
            int pos = o + atomicAdd(&s_bc[b], 1);
            if (pos < 2048) s_sk[pos] = key;
        }
    }
    __syncthreads();

    // phase 3: per-bucket insertion sort
    #pragma unroll
    for (int u = 0; u < SCAN_U; u++) {
        int b = NHIST - 1 - (t * SCAN_U + u);
        int o = s_off[b];
        if (o < 2048) {
            int end = min(o + s_bc[b], 2048);
            for (int i = o + 1; i < end; i++) {
                unsigned long long v = s_sk[i];
                int j = i - 1;
                while (j >= o && s_sk[j] < v) { s_sk[j + 1] = s_sk[j]; j--; }
                s_sk[j + 1] = v;
            }
        }
    }
    __syncthreads();

    // phase 4: labels + validity bitmap + export keys
    for (int i = t; i < 32 * 80; i += 1024) s_ccnt[i] = 0;
    #pragma unroll
    for (int it = 0; it < 2; it++) {
        int r = t + it * 1024;
        unsigned long long key = s_sk[r];
        g_skeys[img][r] = key;
        float sc = __uint_as_float((unsigned)(key >> 32));
        bool valid = (r < KPRE) && (sc > SCORE_THR);
        int lab = valid ? ((int)(~(unsigned)key) % CC) : 0xFFFF;
        s_lab[r] = (unsigned short)lab;
        unsigned bal = __ballot_sync(0xffffffffu, valid);
        if (lane == 0) g_kept[img][r >> 5] = bal;
    }
    __syncthreads();

    // phase 5a: per-warp-chunk class counts
    #pragma unroll
    for (int half = 0; half < 2; half++) {
        int r = wid * 64 + half * 32 + lane;
        int lab = s_lab[r];
        if (lab != 0xFFFF) atomicAdd(&s_ccnt[wid * 80 + lab], 1);
    }
    __syncthreads();

    // phase 5b: chunk-exclusive offsets + class starts
    if (t < 80) {
        int acc = 0;
        for (int w2 = 0; w2 < 32; w2++) {
            int v = s_ccnt[w2 * 80 + t];
            s_ccnt[w2 * 80 + t] = acc;
            acc += v;
        }
        s_tot[t] = acc;
        g_tot[img][t] = acc;
    }
    __syncthreads();
    if (t == 0) {
        int a = 0;
        for (int c2 = 0; c2 < 80; c2++) { s_start[c2] = a; a += s_tot[c2]; }
    }
    __syncthreads();
    if (t < 80) g_start[img][t] = s_start[t];

    // phase 5c: stable scatter into class groups
    #pragma unroll
    for (int half = 0; half < 2; half++) {
        int r = wid * 64 + half * 32 + lane;
        int lab = s_lab[r];
        bool valid = lab != 0xFFFF;
        unsigned key = valid ? (unsigned)lab : (0x100u + lane);
        unsigned mk = __match_any_sync(0xffffffffu, key);
        if (valid) {
            int rank = __popc(mk & lmlt);
            int pos = s_start[lab] + s_ccnt[wid * 80 + lab] + rank;
            s_ord[pos] = (unsigned short)r;
        }
        __syncwarp();
        if (valid && (mk & lmlt) == 0u) s_ccnt[wid * 80 + lab] += __popc(mk);
        __syncwarp();
    }
    __syncthreads();
    g_ord[img][t] = s_ord[t];
    g_ord[img][t + 1024] = s_ord[t + 1024];
}

// -------- NMS (warp per class, register chain) + fused last-block emit ---------
__global__ void k_nms(const float* __restrict__ reg,
                      const float* __restrict__ props,
                      const int* __restrict__ hw,
                      float* __restrict__ out) {
    __shared__ int s_last;
    __shared__ int s_wpre[64];
    __shared__ int s_kcnt;

    int img = blockIdx.x;
    int lane = threadIdx.x & 31, wid = threadIdx.x >> 5;
    int c = blockIdx.y * 8 + wid;
    int st = g_start[img][c], tot = g_tot[img][c];

    float h = (float)hw[img * 2 + 0];
    float w = (float)hw[img * 2 + 1];
    float maxhw1 = __fadd_rn(fmaxf(h, w), 1.0f);

    if (tot != 0) {
        if (tot <= 256) {
            int nr = (tot + 31) >> 5;
            float4 bb[8];
            float aa[8];
            int idxs[8];
            unsigned kmask = 0;
            #pragma unroll
            for (int u = 0; u < 8; u++) {
                idxs[u] = -1;
                bb[u] = make_float4(0, 0, 0, 0);
                aa[u] = 0.0f;
                if (u < nr) {
                    int pos = u * 32 + lane;
                    if (pos < tot) {
                        int idx = g_ord[img][st + pos];
                        idxs[u] = idx;
                        unsigned long long key = g_skeys[img][idx];
                        float4 bx;
                        decode_one(key, img, reg, props, h, w, maxhw1,
                                   &bx, &bb[u], &aa[u]);
                        g_box[img][idx] = bx;
                        kmask |= 1u << u;
                    }
                }
            }
            #pragma unroll
            for (int u = 0; u < 8; u++) {
                if (u >= nr) break;
                int ilim = min(tot - u * 32, 32);
                for (int li = 0; li < ilim; li++) {
                    unsigned am = __ballot_sync(0xffffffffu, (kmask >> u) & 1u);
                    if (!((am >> li) & 1u)) continue;
                    int i = u * 32 + li;
                    float bix = __shfl_sync(0xffffffffu, bb[u].x, li);
                    float biy = __shfl_sync(0xffffffffu, bb[u].y, li);
                    float biz = __shfl_sync(0xffffffffu, bb[u].z, li);
                    float biw = __shfl_sync(0xffffffffu, bb[u].w, li);
                    float ai  = __shfl_sync(0xffffffffu, aa[u], li);
                    float4 bi = make_float4(bix, biy, biz, biw);
                    #pragma unroll
                    for (int v = 0; v < 8; v++) {
                        if (v >= nr) break;
                        int pos = v * 32 + lane;
                        if (pos > i && ((kmask >> v) & 1u)) {
                            if (iou_gt(bi, ai, bb[v], aa[v]))
                                kmask &= ~(1u << v);
                        }
                    }
                }
            }
            #pragma unroll
            for (int u = 0; u < 8; u++) {
                if (u >= nr) break;
                int idx = idxs[u];
                if (idx >= 0 && !((kmask >> u) & 1u))
                    atomicAnd(&g_kept[img][idx >> 5], ~(1u << (idx & 31)));
            }
        } else {
            // slow path (class > 256 candidates; effectively never hit)
            for (int pos = lane; pos < tot; pos += 32) {
                int idx = g_ord[img][st + pos];
                unsigned long long key = g_skeys[img][idx];
                float4 bx, ob;
                float ar;
                decode_one(key, img, reg, props, h, w, maxhw1, &bx, &ob, &ar);
                g_box[img][idx] = bx;
                g_ob[img][idx] = ob;
                g_ar[img][idx] = ar;
            }
            __syncwarp();
            __threadfence();
            for (int i = 0; i < tot - 1; i++) {
                int ri = g_ord[img][st + i];
                if (g_kept[img][ri >> 5] & (1u << (ri & 31))) {
                    float4 bi = g_ob[img][ri];
                    float ai = g_ar[img][ri];
                    for (int j = i + 1 + lane; j < tot; j += 32) {
                        int rj = g_ord[img][st + j];
                        if (g_kept[img][rj >> 5] & (1u << (rj & 31))) {
                            if (iou_gt(bi, ai, g_ob[img][rj], g_ar[img][rj]))
                                atomicAnd(&g_kept[img][rj >> 5], ~(1u << (rj & 31)));
                        }
                    }
                }
                __syncwarp();
                __threadfence();
            }
        }
    }

    // ---- last-block-done protocol: the 10th finishing block emits -------------
    __syncthreads();
    if (threadIdx.x == 0) {
        __threadfence();
        int old = atomicAdd(&g_done[img], 1);
        s_last = (old == 9) ? 1 : 0;
    }
    __syncthreads();
    if (!s_last) return;

    // ---- emit: prefix popcount over kept bitmap + gather (256 threads) --------
    int t = threadIdx.x;
    if (wid == 0) {
        unsigned k0 = __ldcg(&g_kept[img][lane]);
        unsigned k1 = __ldcg(&g_kept[img][32 + lane]);
        int v0 = __popc(k0);
        int v1 = __popc(k1);
        int s0 = v0, s1 = v1;
        #pragma unroll
        for (int o = 1; o < 32; o <<= 1) {
            int x = __shfl_up_sync(0xffffffffu, s0, o);
            if (lane >= o) s0 += x;
            int y = __shfl_up_sync(0xffffffffu, s1, o);
            if (lane >= o) s1 += y;
        }
        int t0 = __shfl_sync(0xffffffffu, s0, 31);
        s_wpre[lane] = s0 - v0;
        s_wpre[32 + lane] = t0 + s1 - v1;
        if (lane == 31) s_kcnt = t0 + s1;
    }
    __syncthreads();

    int kc = s_kcnt;
    if (t < MAXOUT && t >= kc) {
        float* bo = out + (size_t)(img * MAXOUT + t) * 4;
        bo[0] = 0.0f; bo[1] = 0.0f; bo[2] = 0.0f; bo[3] = 0.0f;
        out[BB * MAXOUT * 4 + img * MAXOUT + t] = 0.0f;
        out[BB * MAXOUT * 5 + img * MAXOUT + t] = -1.0f;
    }
    for (int r = t; r < 2048; r += 256) {
        unsigned wrd = __ldcg(&g_kept[img][r >> 5]);
        if (wrd & (1u << (r & 31))) {
            int rank = s_wpre[r >> 5] + __popc(wrd & ((1u << (r & 31)) - 1u));
            if (rank < MAXOUT) {
                float4 bx = __ldcg(&g_box[img][r]);
                unsigned long long key = g_skeys[img][r];
                float sc = __uint_as_float((unsigned)(key >> 32));
                float lb = (float)((int)(~(unsigned)key) % CC);
                float* bo = out + (size_t)(img * MAXOUT + rank) * 4;
                bo[0] = bx.x; bo[1] = bx.y; bo[2] = bx.z; bo[3] = bx.w;
                out[BB * MAXOUT * 4 + img * MAXOUT + rank] = sc;
                out[BB * MAXOUT * 5 + img * MAXOUT + rank] = lb;
            }
        }
    }
    if (t == 0) g_done[img] = 0;   // self-clean for next run
}

// ---------------- launch (3 kernels) -------------------------------------------
extern "C" void kernel_launch(void* const* d_in, const int* in_sizes, int n_in,
                              void* d_out, int out_size) {
    const float* cls = (const float*)d_in[0];
    const float* reg = (const float*)d_in[1];
    const float* props = (const float*)d_in[2];
    const int* hw = (const int*)d_in[3];
    float* out = (float*)d_out;

    cudaFuncSetAttribute(k_sortgroup, cudaFuncAttributeMaxDynamicSharedMemorySize, SMEMSZ);

    k_softmax<<<(BB * NN / 2 * 32 + 255) / 256, 256>>>(cls);
    k_sortgroup<<<BB, 1024, SMEMSZ>>>();
    dim3 ng(BB, 10);
    k_nms<<<ng, 256>>>(reg, props, hw, out);
}